// round 16
// baseline (speedup 1.0000x reference)
#include <cuda_runtime.h>
#include <cuda_fp16.h>
#include <cstdint>

#define HID 96
#define CIN 192
#define MAXN 120000
#define EPSBN 1e-5f

// ===== conv mma params (K=64 per stage) =====
#define CTM 128
#define CNSTG 81
#define CASTR 144
#define CAHPL (128 * CASTR)
#define CBPL (96 * CASTR)
#define CSTG (CAHPL + CBPL)
#define SMEM_CONV (2 * CSTG)

// ===== linear mma params (K=32 stages) =====
#define ASTRIDE 80
#define AHPL (128 * ASTRIDE)
#define BPL (96 * ASTRIDE)
#define LSTG (2 * AHPL + BPL)
#define SMEM_LIN (2 * LSTG)

__device__ float g_vsum[(size_t)MAXN * CIN];
__device__ float g_cnt[MAXN];
__device__ __half g_vh[(size_t)(MAXN + 1) * CIN];
__device__ float g_acc[(size_t)MAXN * HID];
__device__ float g_bn[2 * HID];
__device__ float g_ss[2 * HID];
__device__ __half g_wh[(size_t)CNSTG * 96 * 64];
__device__ __half g_wlh[6 * 96 * 32];
__device__ int g_nbrT[27 * MAXN];

#define MMA_F16(d, a, b0r, b1r)                                               \
    asm volatile(                                                             \
        "mma.sync.aligned.m16n8k16.row.col.f32.f16.f16.f32 "                  \
        "{%0,%1,%2,%3},{%4,%5,%6,%7},{%8,%9},{%0,%1,%2,%3};"                  \
        : "+f"((d)[0]), "+f"((d)[1]), "+f"((d)[2]), "+f"((d)[3])              \
        : "r"((a)[0]), "r"((a)[1]), "r"((a)[2]), "r"((a)[3]),                 \
          "r"(b0r), "r"(b1r))

#define LDMX4(r, addr)                                                        \
    asm volatile(                                                             \
        "ldmatrix.sync.aligned.m8n8.x4.shared.b16 {%0,%1,%2,%3}, [%4];"       \
        : "=r"((r)[0]), "=r"((r)[1]), "=r"((r)[2]), "=r"((r)[3])              \
        : "r"(addr))

__device__ __forceinline__ uint32_t smem_u32(const void* p) {
    uint32_t a;
    asm("{ .reg .u64 t; cvta.to.shared.u64 t, %1; cvt.u32.u64 %0, t; }" : "=r"(a) : "l"(p));
    return a;
}
__device__ __forceinline__ uint32_t pack_h2(float x, float y) {
    __half2 t = __floats2half2_rn(x, y);
    return *reinterpret_cast<uint32_t*>(&t);
}

// ---- 0a: weight prep ----
__global__ void prep_kernel(const float* __restrict__ W, const float* __restrict__ Wl) {
    int b = blockIdx.x;
    if (b < CNSTG) {
        int k = b / 3, ch2 = b - k * 3;
        __half* dst = g_wh + (size_t)b * 6144;
        for (int idx = threadIdx.x; idx < 6144; idx += blockDim.x) {
            int n = idx >> 6;
            int c = idx & 63;
            dst[idx] = __float2half_rn(W[((size_t)k * CIN + (ch2 * 64 + c)) * HID + n]);
        }
    } else {
        int st = b - CNSTG;
        __half* dst = g_wlh + (size_t)st * 3072;
        for (int idx = threadIdx.x; idx < 3072; idx += blockDim.x) {
            int n = idx >> 5;
            int c = idx & 31;
            dst[idx] = __float2half_rn(Wl[(size_t)(st * 32 + c) * HID + n]);
        }
    }
}

// ---- 0b: transpose neighbor table ----
__global__ void nbrT_kernel(const int* __restrict__ nbr, int M) {
    int idx = blockIdx.x * blockDim.x + threadIdx.x;
    if (idx >= M * 27) return;
    int m = idx / 27, k = idx - m * 27;
    g_nbrT[k * MAXN + m] = nbr[idx];
}

// ---- 1: concat + scatter-add ----
__global__ void scatter_kernel(const float* __restrict__ hF, const float* __restrict__ qF,
                               const int* __restrict__ seg, int N) {
    long long t = (long long)blockIdx.x * blockDim.x + threadIdx.x;
    if (t >= (long long)N * (CIN / 4)) return;
    int n = (int)(t / (CIN / 4));
    int c4 = (int)(t - (long long)n * (CIN / 4)) * 4;
    int m = seg[n];
    float4 v = (c4 < HID) ? *(const float4*)(hF + (size_t)n * HID + c4)
                          : *(const float4*)(qF + (size_t)n * HID + (c4 - HID));
    float* dst = g_vsum + (size_t)m * CIN + c4;
    atomicAdd(dst, v.x);
    atomicAdd(dst + 1, v.y);
    atomicAdd(dst + 2, v.z);
    atomicAdd(dst + 3, v.w);
    if (c4 == 0) atomicAdd(&g_cnt[m], 1.0f);
}

// ---- 2: divide by count + fp16 convert ----
__global__ void split_kernel(int M) {
    long long q = (long long)blockIdx.x * blockDim.x + threadIdx.x;
    if (q >= (long long)(M + 1) * (CIN / 4)) return;
    int m = (int)(q / (CIN / 4));
    uint2 o = make_uint2(0u, 0u);
    if (m < M) {
        float ct = g_cnt[m];
        if (ct < 1.0f) ct = 1.0f;
        float inv = 1.0f / ct;
        float4 v = *((const float4*)g_vsum + q);
        o.x = pack_h2(v.x * inv, v.y * inv);
        o.y = pack_h2(v.z * inv, v.w * inv);
    }
    *((uint2*)g_vh + q) = o;
}

// ---- 3: sparse conv, K=64 stages (unchanged R15) ----
__global__ __launch_bounds__(256, 2)
void conv_mma_kernel(int M) {
    extern __shared__ char smem[];
    int tid = threadIdx.x;
    int wid = tid >> 5;
    int lane = tid & 31;
    int mbase = blockIdx.x * CTM;

    int prow = tid >> 1;
    int ppart = tid & 1;
    int warp_m = wid & 3;
    int warp_n = wid >> 2;
    int r0 = lane >> 2;

    uint32_t aoff = (uint32_t)(lane & 15) * CASTR + (uint32_t)(lane >> 4) * 16;
    uint32_t boff = ((uint32_t)(lane & 7) + (uint32_t)(lane >> 4) * 8) * CASTR
                  + (uint32_t)((lane >> 3) & 1) * 16;

    uint32_t sm0 = smem_u32(smem);

    float acc[2][6][4];
#pragma unroll
    for (int mt = 0; mt < 2; ++mt)
#pragma unroll
        for (int nt = 0; nt < 6; ++nt)
#pragma unroll
            for (int q = 0; q < 4; ++q) acc[mt][nt][q] = 0.0f;

    const char* vh = (const char*)g_vh;
    const char* whbase = (const char*)g_wh;
    int pm = mbase + prow;
    bool pok = (pm < M);

    int curRow = pok ? g_nbrT[0 * MAXN + pm] : M;

    {
        const char* sa = vh + (size_t)curRow * 384 + ppart * 64;
        char* da = smem + prow * CASTR + ppart * 64;
        *(uint4*)(da) = *(const uint4*)(sa);
        *(uint4*)(da + 16) = *(const uint4*)(sa + 16);
        *(uint4*)(da + 32) = *(const uint4*)(sa + 32);
        *(uint4*)(da + 48) = *(const uint4*)(sa + 48);
        char* bb = smem + CAHPL;
        const uint4* ws = (const uint4*)whbase;
#pragma unroll
        for (int p = 0; p < 3; ++p) {
            int idx = tid + p * 256;
            uint4 v = ws[idx];
            *(uint4*)(bb + (idx >> 3) * CASTR + (idx & 7) * 16) = v;
        }
    }
    __syncthreads();

    for (int it = 0; it < CNSTG; ++it) {
        int buf = it & 1;
        bool pf = (it + 1 < CNSTG);
        uint4 va[4], vb[3];

        if (pf) {
            int st = it + 1;
            int k = st / 3, ch = st - k * 3;
            if (ch == 0) curRow = pok ? g_nbrT[k * MAXN + pm] : M;
            const char* sa = vh + (size_t)curRow * 384 + ch * 128 + ppart * 64;
            va[0] = *(const uint4*)(sa);
            va[1] = *(const uint4*)(sa + 16);
            va[2] = *(const uint4*)(sa + 32);
            va[3] = *(const uint4*)(sa + 48);
            const uint4* ws = (const uint4*)(whbase + (size_t)st * 12288);
#pragma unroll
            for (int p = 0; p < 3; ++p) vb[p] = ws[tid + p * 256];
        }

        {
            uint32_t ah_u = sm0 + buf * CSTG;
            uint32_t bh_u = ah_u + CAHPL;
            uint32_t atile = (uint32_t)(warp_m * 32) * CASTR + aoff;
            uint32_t btile = (uint32_t)(warp_n * 48) * CASTR + boff;
#pragma unroll
            for (int s = 0; s < 4; ++s) {
                uint32_t kb = s * 32;
                uint32_t Ah[2][4], Bq[3][4];
#pragma unroll
                for (int mt = 0; mt < 2; ++mt) {
                    LDMX4(Ah[mt], ah_u + atile + mt * (16 * CASTR) + kb);
                }
#pragma unroll
                for (int np = 0; np < 3; ++np) {
                    LDMX4(Bq[np], bh_u + btile + np * (16 * CASTR) + kb);
                }
#pragma unroll
                for (int np = 0; np < 3; ++np) {
#pragma unroll
                    for (int mt = 0; mt < 2; ++mt) {
                        MMA_F16(acc[mt][2 * np], Ah[mt], Bq[np][0], Bq[np][1]);
                        MMA_F16(acc[mt][2 * np + 1], Ah[mt], Bq[np][2], Bq[np][3]);
                    }
                }
            }
        }

        if (pf) {
            char* stg = smem + (buf ^ 1) * CSTG;
            char* da = stg + prow * CASTR + ppart * 64;
            *(uint4*)(da) = va[0];
            *(uint4*)(da + 16) = va[1];
            *(uint4*)(da + 32) = va[2];
            *(uint4*)(da + 48) = va[3];
            char* bb = stg + CAHPL;
#pragma unroll
            for (int p = 0; p < 3; ++p) {
                int idx = tid + p * 256;
                *(uint4*)(bb + (idx >> 3) * CASTR + (idx & 7) * 16) = vb[p];
            }
        }
        __syncthreads();
    }

    int cc = (lane & 3) << 1;
#pragma unroll
    for (int mt = 0; mt < 2; ++mt) {
        int row = mbase + warp_m * 32 + mt * 16 + r0;
#pragma unroll
        for (int nt = 0; nt < 6; ++nt) {
            int col = warp_n * 48 + nt * 8 + cc;
            if (row < M)
                *(float2*)(g_acc + (size_t)row * HID + col) =
                    make_float2(acc[mt][nt][0], acc[mt][nt][1]);
            if (row + 8 < M)
                *(float2*)(g_acc + (size_t)(row + 8) * HID + col) =
                    make_float2(acc[mt][nt][2], acc[mt][nt][3]);
        }
    }

    __syncthreads();
    float* bns = (float*)smem;
    float* bnq = bns + 96;
    if (tid < 192) bns[tid] = 0.0f;
    __syncthreads();
#pragma unroll
    for (int nt = 0; nt < 6; ++nt) {
        float s0 = 0.f, q0 = 0.f, s1 = 0.f, q1 = 0.f;
#pragma unroll
        for (int mt = 0; mt < 2; ++mt) {
            int row = mbase + warp_m * 32 + mt * 16 + r0;
            if (row < M) {
                float a = acc[mt][nt][0], b = acc[mt][nt][1];
                s0 += a; q0 += a * a; s1 += b; q1 += b * b;
            }
            if (row + 8 < M) {
                float a = acc[mt][nt][2], b = acc[mt][nt][3];
                s0 += a; q0 += a * a; s1 += b; q1 += b * b;
            }
        }
        int col = warp_n * 48 + nt * 8 + cc;
        atomicAdd(&bns[col], s0);
        atomicAdd(&bnq[col], q0);
        atomicAdd(&bns[col + 1], s1);
        atomicAdd(&bnq[col + 1], q1);
    }
    __syncthreads();
    if (tid < 96) {
        atomicAdd(&g_bn[tid], bns[tid]);
        atomicAdd(&g_bn[96 + tid], bnq[tid]);
    }
}

// ---- 5: BN scale/shift ----
__global__ void bnscale_kernel(const float* __restrict__ gamma,
                               const float* __restrict__ beta, int M) {
    int j = threadIdx.x;
    if (j >= HID) return;
    float inv = 1.0f / (float)M;
    float mu = g_bn[j] * inv;
    float var = g_bn[HID + j] * inv - mu * mu;
    if (var < 0.0f) var = 0.0f;
    float sc = gamma[j] * rsqrtf(var + EPSBN);
    g_ss[j] = sc;
    g_ss[HID + j] = beta[j] - mu * sc;
}

// ---- 7: linear GEMM only (fp16 2-term MMA) -> out = hx@Wl + bl ----
__global__ __launch_bounds__(256, 2)
void linear_mma_kernel(const float* __restrict__ hF, const float* __restrict__ qF,
                       const float* __restrict__ bl,
                       float* __restrict__ out, int N) {
    extern __shared__ char smem[];
    int tid = threadIdx.x;
    int wid = tid >> 5;
    int lane = tid & 31;
    int nbase = blockIdx.x * CTM;

    int prow = tid >> 1;
    int ppart = tid & 1;
    int warp_m = wid & 3;
    int warp_n = wid >> 2;
    int r0 = lane >> 2;

    uint32_t aoff = (uint32_t)(lane & 15) * ASTRIDE + (uint32_t)(lane >> 4) * 16;
    uint32_t boff = ((uint32_t)(lane & 7) + (uint32_t)(lane >> 4) * 8) * ASTRIDE
                  + (uint32_t)((lane >> 3) & 1) * 16;

    uint32_t sm0 = smem_u32(smem);

    float acc[2][6][4];
#pragma unroll
    for (int mt = 0; mt < 2; ++mt)
#pragma unroll
        for (int nt = 0; nt < 6; ++nt)
#pragma unroll
            for (int q = 0; q < 4; ++q) acc[mt][nt][q] = 0.0f;

    const char* wlbase = (const char*)g_wlh;

    {
        int n = nbase + prow;
        float4 v0 = make_float4(0.f, 0.f, 0.f, 0.f), v1 = v0, v2 = v0, v3 = v0;
        if (n < N) {
            const float4* src = (const float4*)(hF + (size_t)n * HID + ppart * 16);
            v0 = src[0]; v1 = src[1]; v2 = src[2]; v3 = src[3];
        }
        char* dh = smem + prow * ASTRIDE + ppart * 32;
        char* dl = dh + AHPL;
        float4 vv[4] = {v0, v1, v2, v3};
#pragma unroll
        for (int i = 0; i < 4; ++i) {
            float4 v = vv[i];
            float hx = __half2float(__float2half_rn(v.x));
            float hy = __half2float(__float2half_rn(v.y));
            float hz = __half2float(__float2half_rn(v.z));
            float hw = __half2float(__float2half_rn(v.w));
            *(uint2*)(dh + i * 8) = make_uint2(pack_h2(hx, hy), pack_h2(hz, hw));
            *(uint2*)(dl + i * 8) = make_uint2(pack_h2(v.x - hx, v.y - hy),
                                               pack_h2(v.z - hz, v.w - hw));
        }
        char* bb = smem + 2 * AHPL;
        const uint4* ws = (const uint4*)wlbase;
        {
            uint4 v = ws[tid];
            *(uint4*)(bb + (tid >> 2) * ASTRIDE + (tid & 3) * 16) = v;
        }
        if (tid < 128) {
            int i2 = tid + 256;
            uint4 v = ws[i2];
            *(uint4*)(bb + (i2 >> 2) * ASTRIDE + (i2 & 3) * 16) = v;
        }
    }
    __syncthreads();

#pragma unroll
    for (int it = 0; it < 6; ++it) {
        int buf = it & 1;
        bool pf = (it + 1 < 6);
        float4 va[4];
        uint4 vb0, vb1;

        if (pf) {
            int st = it + 1;
            int n = nbase + prow;
            va[0] = make_float4(0.f, 0.f, 0.f, 0.f);
            va[1] = va[0]; va[2] = va[0]; va[3] = va[0];
            if (n < N) {
                const float* base = (st < 3) ? (hF + (size_t)n * HID + st * 32)
                                             : (qF + (size_t)n * HID + (st - 3) * 32);
                const float4* src = (const float4*)(base + ppart * 16);
                va[0] = src[0]; va[1] = src[1]; va[2] = src[2]; va[3] = src[3];
            }
            const uint4* ws = (const uint4*)(wlbase + (size_t)st * 6144);
            vb0 = ws[tid];
            if (tid < 128) vb1 = ws[tid + 256];
        }

        {
            uint32_t ah_u = sm0 + buf * LSTG;
            uint32_t al_u = ah_u + AHPL;
            uint32_t bh_u = ah_u + 2 * AHPL;
            uint32_t atile = (uint32_t)(warp_m * 32) * ASTRIDE + aoff;
            uint32_t btile = (uint32_t)(warp_n * 48) * ASTRIDE + boff;
#pragma unroll
            for (int s = 0; s < 2; ++s) {
                uint32_t kb = s * 32;
                uint32_t Ah[2][4], Al[2][4], Bq[3][4];
#pragma unroll
                for (int mt = 0; mt < 2; ++mt) {
                    LDMX4(Ah[mt], ah_u + atile + mt * (16 * ASTRIDE) + kb);
                    LDMX4(Al[mt], al_u + atile + mt * (16 * ASTRIDE) + kb);
                }
#pragma unroll
                for (int np = 0; np < 3; ++np) {
                    LDMX4(Bq[np], bh_u + btile + np * (16 * ASTRIDE) + kb);
                }
#pragma unroll
                for (int np = 0; np < 3; ++np) {
#pragma unroll
                    for (int mt = 0; mt < 2; ++mt) {
                        MMA_F16(acc[mt][2 * np], Ah[mt], Bq[np][0], Bq[np][1]);
                        MMA_F16(acc[mt][2 * np + 1], Ah[mt], Bq[np][2], Bq[np][3]);
                    }
                }
#pragma unroll
                for (int np = 0; np < 3; ++np) {
#pragma unroll
                    for (int mt = 0; mt < 2; ++mt) {
                        MMA_F16(acc[mt][2 * np], Al[mt], Bq[np][0], Bq[np][1]);
                        MMA_F16(acc[mt][2 * np + 1], Al[mt], Bq[np][2], Bq[np][3]);
                    }
                }
            }
        }

        if (pf) {
            char* stg = smem + (buf ^ 1) * LSTG;
            char* dh = stg + prow * ASTRIDE + ppart * 32;
            char* dl = dh + AHPL;
#pragma unroll
            for (int i = 0; i < 4; ++i) {
                float4 v = va[i];
                float hx = __half2float(__float2half_rn(v.x));
                float hy = __half2float(__float2half_rn(v.y));
                float hz = __half2float(__float2half_rn(v.z));
                float hw = __half2float(__float2half_rn(v.w));
                *(uint2*)(dh + i * 8) = make_uint2(pack_h2(hx, hy), pack_h2(hz, hw));
                *(uint2*)(dl + i * 8) = make_uint2(pack_h2(v.x - hx, v.y - hy),
                                                   pack_h2(v.z - hz, v.w - hw));
            }
            char* bb = stg + 2 * AHPL;
            *(uint4*)(bb + (tid >> 2) * ASTRIDE + (tid & 3) * 16) = vb0;
            if (tid < 128) {
                int i2 = tid + 256;
                *(uint4*)(bb + (i2 >> 2) * ASTRIDE + (i2 & 3) * 16) = vb1;
            }
        }
        __syncthreads();
    }

    // ---- epilogue: bias + store (MMA fragment layout) ----
    int cc = (lane & 3) << 1;
#pragma unroll
    for (int mt = 0; mt < 2; ++mt) {
#pragma unroll
        for (int half = 0; half < 2; ++half) {
            int lr = warp_m * 32 + mt * 16 + r0 + half * 8;
            int n = nbase + lr;
            if (n >= N) continue;
#pragma unroll
            for (int nt = 0; nt < 6; ++nt) {
                int col = warp_n * 48 + nt * 8 + cc;
                float s0 = acc[mt][nt][2 * half]     + bl[col];
                float s1 = acc[mt][nt][2 * half + 1] + bl[col + 1];
                *(float2*)(out + (size_t)n * HID + col) = make_float2(s0, s1);
            }
        }
    }
}

// ---- 8: trilinear gather with fused BN+ReLU (accumulate into out) ----
__global__ void trilinear_kernel(const float* __restrict__ cw, const int* __restrict__ cidx,
                                 float* __restrict__ out, int N, int M) {
    long long t = (long long)blockIdx.x * blockDim.x + threadIdx.x;
    if (t >= (long long)N * HID) return;
    int n = (int)(t / HID);
    int j = (int)(t - (long long)n * HID);
    float sc = g_ss[j];
    float sh = g_ss[HID + j];
    float s = out[t];
#pragma unroll
    for (int k = 0; k < 8; ++k) {
        int ci = cidx[(size_t)n * 8 + k];
        if (ci < M) {
            float w = cw[(size_t)n * 8 + k];
            float v = g_acc[(size_t)ci * HID + j] * sc + sh;
            v = v > 0.0f ? v : 0.0f;
            s += w * v;
        }
    }
    out[t] = s;
}

extern "C" void kernel_launch(void* const* d_in, const int* in_sizes, int n_in,
                              void* d_out, int out_size) {
    const float* hF    = (const float*)d_in[0];
    const float* qF    = (const float*)d_in[1];
    const float* Wc    = (const float*)d_in[2];
    const float* gamma = (const float*)d_in[3];
    const float* beta  = (const float*)d_in[4];
    const float* Wl    = (const float*)d_in[5];
    const float* bl    = (const float*)d_in[6];
    const float* cw    = (const float*)d_in[7];
    const int*   seg   = (const int*)d_in[8];
    const int*   nbr   = (const int*)d_in[9];
    const int*   cidx  = (const int*)d_in[10];
    float* out = (float*)d_out;

    int N = in_sizes[8];
    int M = in_sizes[9] / 27;

    cudaFuncSetAttribute(conv_mma_kernel,
                         cudaFuncAttributeMaxDynamicSharedMemorySize, SMEM_CONV);
    cudaFuncSetAttribute(linear_mma_kernel,
                         cudaFuncAttributeMaxDynamicSharedMemorySize, SMEM_LIN);

    void *pv, *pc, *pb;
    cudaGetSymbolAddress(&pv, g_vsum);
    cudaGetSymbolAddress(&pc, g_cnt);
    cudaGetSymbolAddress(&pb, g_bn);

    cudaStream_t s2;
    cudaStreamCreateWithFlags(&s2, cudaStreamNonBlocking);
    cudaEvent_t e0, e1, e2;
    cudaEventCreateWithFlags(&e0, cudaEventDisableTiming);
    cudaEventCreateWithFlags(&e1, cudaEventDisableTiming);
    cudaEventCreateWithFlags(&e2, cudaEventDisableTiming);

    cudaEventRecord(e0, 0);
    cudaStreamWaitEvent(s2, e0, 0);
    prep_kernel<<<CNSTG + 6, 256, 0, s2>>>(Wc, Wl);
    nbrT_kernel<<<(M * 27 + 255) / 256, 256, 0, s2>>>(nbr, M);
    cudaMemsetAsync(pb, 0, 2 * HID * sizeof(float), s2);
    cudaEventRecord(e1, s2);
    // linear GEMM overlaps with scatter/split/conv on main stream
    linear_mma_kernel<<<(N + CTM - 1) / CTM, 256, SMEM_LIN, s2>>>(hF, qF, bl, out, N);
    cudaEventRecord(e2, s2);

    cudaMemsetAsync(pv, 0, (size_t)M * CIN * sizeof(float), 0);
    cudaMemsetAsync(pc, 0, (size_t)M * sizeof(float), 0);

    long long nt;
    nt = (long long)N * (CIN / 4);
    scatter_kernel<<<(unsigned)((nt + 255) / 256), 256>>>(hF, qF, seg, N);

    nt = (long long)(M + 1) * (CIN / 4);
    split_kernel<<<(unsigned)((nt + 255) / 256), 256>>>(M);

    cudaStreamWaitEvent(0, e1, 0);
    conv_mma_kernel<<<(M + CTM - 1) / CTM, 256, SMEM_CONV>>>(M);

    bnscale_kernel<<<1, HID>>>(gamma, beta, M);

    cudaStreamWaitEvent(0, e2, 0);
    nt = (long long)N * HID;
    trilinear_kernel<<<(unsigned)((nt + 255) / 256), 256>>>(cw, cidx, out, N, M);

    cudaEventDestroy(e0);
    cudaEventDestroy(e1);
    cudaEventDestroy(e2);
    cudaStreamDestroy(s2);
}

// round 17
// speedup vs baseline: 1.0820x; 1.0820x over previous
#include <cuda_runtime.h>
#include <cuda_fp16.h>
#include <cstdint>

#define HID 96
#define CIN 192
#define MAXN 120000
#define EPSBN 1e-5f

// ===== conv mma params (K=64 per stage) =====
#define CTM 128
#define CNSTG 81
#define CASTR 144
#define CAHPL (128 * CASTR)
#define CBPL (96 * CASTR)
#define CSTG (CAHPL + CBPL)
#define SMEM_CONV (2 * CSTG)

// ===== linear mma params (K=32 stages) =====
#define ASTRIDE 80
#define AHPL (128 * ASTRIDE)
#define BPL (96 * ASTRIDE)
#define LSTG (2 * AHPL + BPL)
#define SMEM_LIN (2 * LSTG)

__device__ float g_vsum[(size_t)MAXN * CIN];
__device__ float g_cnt[MAXN];
__device__ __half g_vh[(size_t)(MAXN + 1) * CIN];
__device__ float g_acc[(size_t)MAXN * HID];
__device__ float g_bn[2 * HID];
__device__ float g_ss[2 * HID];
__device__ __half g_wh[(size_t)CNSTG * 96 * 64];
__device__ __half g_wlh[6 * 96 * 32];
__device__ int g_nbrT[27 * MAXN];

#define MMA_F16(d, a, b0r, b1r)                                               \
    asm volatile(                                                             \
        "mma.sync.aligned.m16n8k16.row.col.f32.f16.f16.f32 "                  \
        "{%0,%1,%2,%3},{%4,%5,%6,%7},{%8,%9},{%0,%1,%2,%3};"                  \
        : "+f"((d)[0]), "+f"((d)[1]), "+f"((d)[2]), "+f"((d)[3])              \
        : "r"((a)[0]), "r"((a)[1]), "r"((a)[2]), "r"((a)[3]),                 \
          "r"(b0r), "r"(b1r))

#define LDMX4(r, addr)                                                        \
    asm volatile(                                                             \
        "ldmatrix.sync.aligned.m8n8.x4.shared.b16 {%0,%1,%2,%3}, [%4];"       \
        : "=r"((r)[0]), "=r"((r)[1]), "=r"((r)[2]), "=r"((r)[3])              \
        : "r"(addr))

__device__ __forceinline__ uint32_t smem_u32(const void* p) {
    uint32_t a;
    asm("{ .reg .u64 t; cvta.to.shared.u64 t, %1; cvt.u32.u64 %0, t; }" : "=r"(a) : "l"(p));
    return a;
}
__device__ __forceinline__ uint32_t pack_h2(float x, float y) {
    __half2 t = __floats2half2_rn(x, y);
    return *reinterpret_cast<uint32_t*>(&t);
}

// ---- 0a: weight prep ----
__global__ void prep_kernel(const float* __restrict__ W, const float* __restrict__ Wl) {
    int b = blockIdx.x;
    if (b < CNSTG) {
        int k = b / 3, ch2 = b - k * 3;
        __half* dst = g_wh + (size_t)b * 6144;
        for (int idx = threadIdx.x; idx < 6144; idx += blockDim.x) {
            int n = idx >> 6;
            int c = idx & 63;
            dst[idx] = __float2half_rn(W[((size_t)k * CIN + (ch2 * 64 + c)) * HID + n]);
        }
    } else {
        int st = b - CNSTG;
        __half* dst = g_wlh + (size_t)st * 3072;
        for (int idx = threadIdx.x; idx < 3072; idx += blockDim.x) {
            int n = idx >> 5;
            int c = idx & 31;
            dst[idx] = __float2half_rn(Wl[(size_t)(st * 32 + c) * HID + n]);
        }
    }
}

// ---- 0b: transpose neighbor table ----
__global__ void nbrT_kernel(const int* __restrict__ nbr, int M) {
    int idx = blockIdx.x * blockDim.x + threadIdx.x;
    if (idx >= M * 27) return;
    int m = idx / 27, k = idx - m * 27;
    g_nbrT[k * MAXN + m] = nbr[idx];
}

// ---- 1: concat + scatter-add, vectorized red.v4 ----
__global__ void scatter_kernel(const float* __restrict__ hF, const float* __restrict__ qF,
                               const int* __restrict__ seg, int N) {
    long long t = (long long)blockIdx.x * blockDim.x + threadIdx.x;
    if (t >= (long long)N * (CIN / 4)) return;
    int n = (int)(t / (CIN / 4));
    int c4 = (int)(t - (long long)n * (CIN / 4)) * 4;
    int m = seg[n];
    float4 v = (c4 < HID) ? *(const float4*)(hF + (size_t)n * HID + c4)
                          : *(const float4*)(qF + (size_t)n * HID + (c4 - HID));
    float* dst = g_vsum + (size_t)m * CIN + c4;
    asm volatile("red.global.add.v4.f32 [%0], {%1, %2, %3, %4};"
                 :: "l"(dst), "f"(v.x), "f"(v.y), "f"(v.z), "f"(v.w) : "memory");
    if (c4 == 0) atomicAdd(&g_cnt[m], 1.0f);
}

// ---- 2: divide by count + fp16 convert ----
__global__ void split_kernel(int M) {
    long long q = (long long)blockIdx.x * blockDim.x + threadIdx.x;
    if (q >= (long long)(M + 1) * (CIN / 4)) return;
    int m = (int)(q / (CIN / 4));
    uint2 o = make_uint2(0u, 0u);
    if (m < M) {
        float ct = g_cnt[m];
        if (ct < 1.0f) ct = 1.0f;
        float inv = 1.0f / ct;
        float4 v = *((const float4*)g_vsum + q);
        o.x = pack_h2(v.x * inv, v.y * inv);
        o.y = pack_h2(v.z * inv, v.w * inv);
    }
    *((uint2*)g_vh + q) = o;
}

// ---- 3: sparse conv, K=64 stages ----
__global__ __launch_bounds__(256, 2)
void conv_mma_kernel(int M) {
    extern __shared__ char smem[];
    int tid = threadIdx.x;
    int wid = tid >> 5;
    int lane = tid & 31;
    int mbase = blockIdx.x * CTM;

    int prow = tid >> 1;
    int ppart = tid & 1;
    int warp_m = wid & 3;
    int warp_n = wid >> 2;
    int r0 = lane >> 2;

    uint32_t aoff = (uint32_t)(lane & 15) * CASTR + (uint32_t)(lane >> 4) * 16;
    uint32_t boff = ((uint32_t)(lane & 7) + (uint32_t)(lane >> 4) * 8) * CASTR
                  + (uint32_t)((lane >> 3) & 1) * 16;

    uint32_t sm0 = smem_u32(smem);

    float acc[2][6][4];
#pragma unroll
    for (int mt = 0; mt < 2; ++mt)
#pragma unroll
        for (int nt = 0; nt < 6; ++nt)
#pragma unroll
            for (int q = 0; q < 4; ++q) acc[mt][nt][q] = 0.0f;

    const char* vh = (const char*)g_vh;
    const char* whbase = (const char*)g_wh;
    int pm = mbase + prow;
    bool pok = (pm < M);

    int curRow = pok ? g_nbrT[0 * MAXN + pm] : M;

    {
        const char* sa = vh + (size_t)curRow * 384 + ppart * 64;
        char* da = smem + prow * CASTR + ppart * 64;
        *(uint4*)(da) = *(const uint4*)(sa);
        *(uint4*)(da + 16) = *(const uint4*)(sa + 16);
        *(uint4*)(da + 32) = *(const uint4*)(sa + 32);
        *(uint4*)(da + 48) = *(const uint4*)(sa + 48);
        char* bb = smem + CAHPL;
        const uint4* ws = (const uint4*)whbase;
#pragma unroll
        for (int p = 0; p < 3; ++p) {
            int idx = tid + p * 256;
            uint4 v = ws[idx];
            *(uint4*)(bb + (idx >> 3) * CASTR + (idx & 7) * 16) = v;
        }
    }
    __syncthreads();

    for (int it = 0; it < CNSTG; ++it) {
        int buf = it & 1;
        bool pf = (it + 1 < CNSTG);
        uint4 va[4], vb[3];

        if (pf) {
            int st = it + 1;
            int k = st / 3, ch = st - k * 3;
            if (ch == 0) curRow = pok ? g_nbrT[k * MAXN + pm] : M;
            const char* sa = vh + (size_t)curRow * 384 + ch * 128 + ppart * 64;
            va[0] = *(const uint4*)(sa);
            va[1] = *(const uint4*)(sa + 16);
            va[2] = *(const uint4*)(sa + 32);
            va[3] = *(const uint4*)(sa + 48);
            const uint4* ws = (const uint4*)(whbase + (size_t)st * 12288);
#pragma unroll
            for (int p = 0; p < 3; ++p) vb[p] = ws[tid + p * 256];
        }

        {
            uint32_t ah_u = sm0 + buf * CSTG;
            uint32_t bh_u = ah_u + CAHPL;
            uint32_t atile = (uint32_t)(warp_m * 32) * CASTR + aoff;
            uint32_t btile = (uint32_t)(warp_n * 48) * CASTR + boff;
#pragma unroll
            for (int s = 0; s < 4; ++s) {
                uint32_t kb = s * 32;
                uint32_t Ah[2][4], Bq[3][4];
#pragma unroll
                for (int mt = 0; mt < 2; ++mt) {
                    LDMX4(Ah[mt], ah_u + atile + mt * (16 * CASTR) + kb);
                }
#pragma unroll
                for (int np = 0; np < 3; ++np) {
                    LDMX4(Bq[np], bh_u + btile + np * (16 * CASTR) + kb);
                }
#pragma unroll
                for (int np = 0; np < 3; ++np) {
#pragma unroll
                    for (int mt = 0; mt < 2; ++mt) {
                        MMA_F16(acc[mt][2 * np], Ah[mt], Bq[np][0], Bq[np][1]);
                        MMA_F16(acc[mt][2 * np + 1], Ah[mt], Bq[np][2], Bq[np][3]);
                    }
                }
            }
        }

        if (pf) {
            char* stg = smem + (buf ^ 1) * CSTG;
            char* da = stg + prow * CASTR + ppart * 64;
            *(uint4*)(da) = va[0];
            *(uint4*)(da + 16) = va[1];
            *(uint4*)(da + 32) = va[2];
            *(uint4*)(da + 48) = va[3];
            char* bb = stg + CAHPL;
#pragma unroll
            for (int p = 0; p < 3; ++p) {
                int idx = tid + p * 256;
                *(uint4*)(bb + (idx >> 3) * CASTR + (idx & 7) * 16) = vb[p];
            }
        }
        __syncthreads();
    }

    int cc = (lane & 3) << 1;
#pragma unroll
    for (int mt = 0; mt < 2; ++mt) {
        int row = mbase + warp_m * 32 + mt * 16 + r0;
#pragma unroll
        for (int nt = 0; nt < 6; ++nt) {
            int col = warp_n * 48 + nt * 8 + cc;
            if (row < M)
                *(float2*)(g_acc + (size_t)row * HID + col) =
                    make_float2(acc[mt][nt][0], acc[mt][nt][1]);
            if (row + 8 < M)
                *(float2*)(g_acc + (size_t)(row + 8) * HID + col) =
                    make_float2(acc[mt][nt][2], acc[mt][nt][3]);
        }
    }

    __syncthreads();
    float* bns = (float*)smem;
    float* bnq = bns + 96;
    if (tid < 192) bns[tid] = 0.0f;
    __syncthreads();
#pragma unroll
    for (int nt = 0; nt < 6; ++nt) {
        float s0 = 0.f, q0 = 0.f, s1 = 0.f, q1 = 0.f;
#pragma unroll
        for (int mt = 0; mt < 2; ++mt) {
            int row = mbase + warp_m * 32 + mt * 16 + r0;
            if (row < M) {
                float a = acc[mt][nt][0], b = acc[mt][nt][1];
                s0 += a; q0 += a * a; s1 += b; q1 += b * b;
            }
            if (row + 8 < M) {
                float a = acc[mt][nt][2], b = acc[mt][nt][3];
                s0 += a; q0 += a * a; s1 += b; q1 += b * b;
            }
        }
        int col = warp_n * 48 + nt * 8 + cc;
        atomicAdd(&bns[col], s0);
        atomicAdd(&bnq[col], q0);
        atomicAdd(&bns[col + 1], s1);
        atomicAdd(&bnq[col + 1], q1);
    }
    __syncthreads();
    if (tid < 96) {
        atomicAdd(&g_bn[tid], bns[tid]);
        atomicAdd(&g_bn[96 + tid], bnq[tid]);
    }
}

// ---- 5: BN scale/shift ----
__global__ void bnscale_kernel(const float* __restrict__ gamma,
                               const float* __restrict__ beta, int M) {
    int j = threadIdx.x;
    if (j >= HID) return;
    float inv = 1.0f / (float)M;
    float mu = g_bn[j] * inv;
    float var = g_bn[HID + j] * inv - mu * mu;
    if (var < 0.0f) var = 0.0f;
    float sc = gamma[j] * rsqrtf(var + EPSBN);
    g_ss[j] = sc;
    g_ss[HID + j] = beta[j] - mu * sc;
}

// ---- 7: fused linear (fp16 2-term MMA) + trilinear gather ----
__global__ __launch_bounds__(256, 2)
void linear_mma_kernel(const float* __restrict__ hF, const float* __restrict__ qF,
                       const float* __restrict__ bl,
                       const float* __restrict__ cw, const int* __restrict__ cidx,
                       float* __restrict__ out, int N, int M) {
    extern __shared__ char smem[];
    int tid = threadIdx.x;
    int wid = tid >> 5;
    int lane = tid & 31;
    int nbase = blockIdx.x * CTM;

    int prow = tid >> 1;
    int ppart = tid & 1;
    int warp_m = wid & 3;
    int warp_n = wid >> 2;
    int r0 = lane >> 2;

    uint32_t aoff = (uint32_t)(lane & 15) * ASTRIDE + (uint32_t)(lane >> 4) * 16;
    uint32_t boff = ((uint32_t)(lane & 7) + (uint32_t)(lane >> 4) * 8) * ASTRIDE
                  + (uint32_t)((lane >> 3) & 1) * 16;

    uint32_t sm0 = smem_u32(smem);

    float acc[2][6][4];
#pragma unroll
    for (int mt = 0; mt < 2; ++mt)
#pragma unroll
        for (int nt = 0; nt < 6; ++nt)
#pragma unroll
            for (int q = 0; q < 4; ++q) acc[mt][nt][q] = 0.0f;

    const char* wlbase = (const char*)g_wlh;

    {
        int n = nbase + prow;
        float4 v0 = make_float4(0.f, 0.f, 0.f, 0.f), v1 = v0, v2 = v0, v3 = v0;
        if (n < N) {
            const float4* src = (const float4*)(hF + (size_t)n * HID + ppart * 16);
            v0 = src[0]; v1 = src[1]; v2 = src[2]; v3 = src[3];
        }
        char* dh = smem + prow * ASTRIDE + ppart * 32;
        char* dl = dh + AHPL;
        float4 vv[4] = {v0, v1, v2, v3};
#pragma unroll
        for (int i = 0; i < 4; ++i) {
            float4 v = vv[i];
            float hx = __half2float(__float2half_rn(v.x));
            float hy = __half2float(__float2half_rn(v.y));
            float hz = __half2float(__float2half_rn(v.z));
            float hw = __half2float(__float2half_rn(v.w));
            *(uint2*)(dh + i * 8) = make_uint2(pack_h2(hx, hy), pack_h2(hz, hw));
            *(uint2*)(dl + i * 8) = make_uint2(pack_h2(v.x - hx, v.y - hy),
                                               pack_h2(v.z - hz, v.w - hw));
        }
        char* bb = smem + 2 * AHPL;
        const uint4* ws = (const uint4*)wlbase;
        {
            uint4 v = ws[tid];
            *(uint4*)(bb + (tid >> 2) * ASTRIDE + (tid & 3) * 16) = v;
        }
        if (tid < 128) {
            int i2 = tid + 256;
            uint4 v = ws[i2];
            *(uint4*)(bb + (i2 >> 2) * ASTRIDE + (i2 & 3) * 16) = v;
        }
    }
    __syncthreads();

#pragma unroll
    for (int it = 0; it < 6; ++it) {
        int buf = it & 1;
        bool pf = (it + 1 < 6);
        float4 va[4];
        uint4 vb0, vb1;

        if (pf) {
            int st = it + 1;
            int n = nbase + prow;
            va[0] = make_float4(0.f, 0.f, 0.f, 0.f);
            va[1] = va[0]; va[2] = va[0]; va[3] = va[0];
            if (n < N) {
                const float* base = (st < 3) ? (hF + (size_t)n * HID + st * 32)
                                             : (qF + (size_t)n * HID + (st - 3) * 32);
                const float4* src = (const float4*)(base + ppart * 16);
                va[0] = src[0]; va[1] = src[1]; va[2] = src[2]; va[3] = src[3];
            }
            const uint4* ws = (const uint4*)(wlbase + (size_t)st * 6144);
            vb0 = ws[tid];
            if (tid < 128) vb1 = ws[tid + 256];
        }

        {
            uint32_t ah_u = sm0 + buf * LSTG;
            uint32_t al_u = ah_u + AHPL;
            uint32_t bh_u = ah_u + 2 * AHPL;
            uint32_t atile = (uint32_t)(warp_m * 32) * ASTRIDE + aoff;
            uint32_t btile = (uint32_t)(warp_n * 48) * ASTRIDE + boff;
#pragma unroll
            for (int s = 0; s < 2; ++s) {
                uint32_t kb = s * 32;
                uint32_t Ah[2][4], Al[2][4], Bq[3][4];
#pragma unroll
                for (int mt = 0; mt < 2; ++mt) {
                    LDMX4(Ah[mt], ah_u + atile + mt * (16 * ASTRIDE) + kb);
                    LDMX4(Al[mt], al_u + atile + mt * (16 * ASTRIDE) + kb);
                }
#pragma unroll
                for (int np = 0; np < 3; ++np) {
                    LDMX4(Bq[np], bh_u + btile + np * (16 * ASTRIDE) + kb);
                }
#pragma unroll
                for (int np = 0; np < 3; ++np) {
#pragma unroll
                    for (int mt = 0; mt < 2; ++mt) {
                        MMA_F16(acc[mt][2 * np], Ah[mt], Bq[np][0], Bq[np][1]);
                        MMA_F16(acc[mt][2 * np + 1], Ah[mt], Bq[np][2], Bq[np][3]);
                    }
                }
#pragma unroll
                for (int np = 0; np < 3; ++np) {
#pragma unroll
                    for (int mt = 0; mt < 2; ++mt) {
                        MMA_F16(acc[mt][2 * np], Al[mt], Bq[np][0], Bq[np][1]);
                        MMA_F16(acc[mt][2 * np + 1], Al[mt], Bq[np][2], Bq[np][3]);
                    }
                }
            }
        }

        if (pf) {
            char* stg = smem + (buf ^ 1) * LSTG;
            char* dh = stg + prow * ASTRIDE + ppart * 32;
            char* dl = dh + AHPL;
#pragma unroll
            for (int i = 0; i < 4; ++i) {
                float4 v = va[i];
                float hx = __half2float(__float2half_rn(v.x));
                float hy = __half2float(__float2half_rn(v.y));
                float hz = __half2float(__float2half_rn(v.z));
                float hw = __half2float(__float2half_rn(v.w));
                *(uint2*)(dh + i * 8) = make_uint2(pack_h2(hx, hy), pack_h2(hz, hw));
                *(uint2*)(dl + i * 8) = make_uint2(pack_h2(v.x - hx, v.y - hy),
                                                   pack_h2(v.z - hz, v.w - hw));
            }
            char* bb = stg + 2 * AHPL;
            *(uint4*)(bb + (tid >> 2) * ASTRIDE + (tid & 3) * 16) = vb0;
            if (tid < 128) {
                int i2 = tid + 256;
                *(uint4*)(bb + (i2 >> 2) * ASTRIDE + (i2 & 3) * 16) = vb1;
            }
        }
        __syncthreads();
    }

    int* sci = (int*)smem;
    float* scw = (float*)smem + 1024;
    for (int idx = tid; idx < 1024; idx += 256) {
        int n = nbase + (idx >> 3);
        int k = idx & 7;
        sci[idx] = (n < N) ? cidx[(size_t)n * 8 + k] : M;
        scw[idx] = (n < N) ? cw[(size_t)n * 8 + k] : 0.0f;
    }
    __syncthreads();

    int cc = (lane & 3) << 1;
#pragma unroll
    for (int mt = 0; mt < 2; ++mt) {
#pragma unroll
        for (int half = 0; half < 2; ++half) {
            int lr = warp_m * 32 + mt * 16 + r0 + half * 8;
            int n = nbase + lr;
            if (n >= N) continue;
#pragma unroll
            for (int nt = 0; nt < 6; ++nt) {
                int col = warp_n * 48 + nt * 8 + cc;
                float s0 = acc[mt][nt][2 * half]     + bl[col];
                float s1 = acc[mt][nt][2 * half + 1] + bl[col + 1];
                float c0 = g_ss[col], c1 = g_ss[col + 1];
                float h0 = g_ss[HID + col], h1 = g_ss[HID + col + 1];
#pragma unroll
                for (int k = 0; k < 8; ++k) {
                    int ci = sci[lr * 8 + k];
                    if (ci < M) {
                        float w = scw[lr * 8 + k];
                        float2 v = *(const float2*)(g_acc + (size_t)ci * HID + col);
                        s0 += w * fmaxf(v.x * c0 + h0, 0.0f);
                        s1 += w * fmaxf(v.y * c1 + h1, 0.0f);
                    }
                }
                *(float2*)(out + (size_t)n * HID + col) = make_float2(s0, s1);
            }
        }
    }
}

extern "C" void kernel_launch(void* const* d_in, const int* in_sizes, int n_in,
                              void* d_out, int out_size) {
    const float* hF    = (const float*)d_in[0];
    const float* qF    = (const float*)d_in[1];
    const float* Wc    = (const float*)d_in[2];
    const float* gamma = (const float*)d_in[3];
    const float* beta  = (const float*)d_in[4];
    const float* Wl    = (const float*)d_in[5];
    const float* bl    = (const float*)d_in[6];
    const float* cw    = (const float*)d_in[7];
    const int*   seg   = (const int*)d_in[8];
    const int*   nbr   = (const int*)d_in[9];
    const int*   cidx  = (const int*)d_in[10];
    float* out = (float*)d_out;

    int N = in_sizes[8];
    int M = in_sizes[9] / 27;

    cudaFuncSetAttribute(conv_mma_kernel,
                         cudaFuncAttributeMaxDynamicSharedMemorySize, SMEM_CONV);
    cudaFuncSetAttribute(linear_mma_kernel,
                         cudaFuncAttributeMaxDynamicSharedMemorySize, SMEM_LIN);

    void *pv, *pc, *pb;
    cudaGetSymbolAddress(&pv, g_vsum);
    cudaGetSymbolAddress(&pc, g_cnt);
    cudaGetSymbolAddress(&pb, g_bn);

    cudaStream_t s2;
    cudaStreamCreateWithFlags(&s2, cudaStreamNonBlocking);
    cudaEvent_t e0, e1;
    cudaEventCreateWithFlags(&e0, cudaEventDisableTiming);
    cudaEventCreateWithFlags(&e1, cudaEventDisableTiming);

    cudaEventRecord(e0, 0);
    cudaStreamWaitEvent(s2, e0, 0);
    prep_kernel<<<CNSTG + 6, 256, 0, s2>>>(Wc, Wl);
    nbrT_kernel<<<(M * 27 + 255) / 256, 256, 0, s2>>>(nbr, M);
    cudaMemsetAsync(pb, 0, 2 * HID * sizeof(float), s2);
    cudaEventRecord(e1, s2);

    cudaMemsetAsync(pv, 0, (size_t)M * CIN * sizeof(float), 0);
    cudaMemsetAsync(pc, 0, (size_t)M * sizeof(float), 0);

    long long nt;
    nt = (long long)N * (CIN / 4);
    scatter_kernel<<<(unsigned)((nt + 255) / 256), 256>>>(hF, qF, seg, N);

    nt = (long long)(M + 1) * (CIN / 4);
    split_kernel<<<(unsigned)((nt + 255) / 256), 256>>>(M);

    cudaStreamWaitEvent(0, e1, 0);
    conv_mma_kernel<<<(M + CTM - 1) / CTM, 256, SMEM_CONV>>>(M);

    bnscale_kernel<<<1, HID>>>(gamma, beta, M);

    linear_mma_kernel<<<(N + CTM - 1) / CTM, 256, SMEM_LIN>>>(
        hF, qF, bl, cw, cidx, out, N, M);

    cudaEventDestroy(e0);
    cudaEventDestroy(e1);
    cudaStreamDestroy(s2);
}